// round 9
// baseline (speedup 1.0000x reference)
#include <cuda_runtime.h>
#include <cuda_fp16.h>
#include <math.h>
#include <stdint.h>

#define BB   2
#define CIN  16
#define NG   6
#define CG   16
#define NOC  96
#define TT   31
#define HH   128
#define WW   128
#define HWSZ (HH*WW)

#define PH   16
#define PW   16
#define NTHR 384            // 12 warps

// smem:
//   xt  [3][18][18][24] halves at 0      : 46656 B
//   B9  [9][96][24] halves     at 46656  : 41472 B
//   W32 [9][16][96] floats     at 88128  : 55296 B
#define CIP      24
#define XT_BYTES (3*18*18*CIP*2)
#define B9_OFF   XT_BYTES
#define B9_BYTES (9*NOC*CIP*2)
#define W32_OFF  (B9_OFF + B9_BYTES)
#define W32_BYTES (9*CIN*NOC*4)
#define SMEM_DYN (W32_OFF + W32_BYTES)   // 143424

#define RS  (CIP*2)   // 48B xt/B9 row stride

// gates scratch [g][b][c][t][h][w]
__device__ float g_gates[(size_t)NG * BB * CG * TT * HWSZ];
// fp16 weights [j=27][oc=96][ci=16]
__device__ __align__(16) __half g_wH[27 * NOC * CIN];
// f32 weights [j=27][ci=16][oc=96]
__device__ __align__(16) float g_w32[27 * CIN * NOC];

// ---------------- helpers ----------------
__device__ __forceinline__ uint32_t smem_u32(const void* p) {
    uint32_t a;
    asm("{ .reg .u64 t; cvta.to.shared.u64 t, %1; cvt.u32.u64 %0, t; }"
        : "=r"(a) : "l"(p));
    return a;
}
__device__ __forceinline__ float ex2f(float z) {
    float r; asm("ex2.approx.f32 %0, %1;" : "=f"(r) : "f"(z)); return r;
}
__device__ __forceinline__ float rcpn(float d) {
    float r; asm("rcp.approx.f32 %0, %1;" : "=f"(r) : "f"(d));
    return r * fmaf(-d, r, 2.0f);
}
__device__ __forceinline__ float sigf(float v) {
    v = fminf(fmaxf(v, -80.f), 80.f);
    return rcpn(1.0f + ex2f(-1.442695041f * v));
}
__device__ __forceinline__ float tanhfst(float v) {
    v = fminf(fmaxf(v, -40.f), 40.f);
    return fmaf(2.0f, rcpn(1.0f + ex2f(-2.885390082f * v)), -1.0f);
}
__device__ __forceinline__ void fma2(unsigned long long& d,
                                     unsigned long long a,
                                     unsigned long long b)
{
    asm("fma.rn.f32x2 %0, %1, %2, %0;" : "+l"(d) : "l"(a), "l"(b));
}
__device__ __forceinline__ unsigned long long dup2(float v)
{
    unsigned long long r;
    asm("mov.b64 %0, {%1, %1};" : "=l"(r) : "f"(v));
    return r;
}
__device__ __forceinline__ void unpack2(unsigned long long p, float& lo, float& hi)
{
    asm("mov.b64 {%0, %1}, %2;" : "=f"(lo), "=f"(hi) : "l"(p));
}

#define MMA_F16(c, a0, a1, a2, a3, b0, b1)                                    \
    asm volatile("mma.sync.aligned.m16n8k16.row.col.f32.f16.f16.f32 "         \
                 "{%0,%1,%2,%3}, {%4,%5,%6,%7}, {%8,%9}, {%0,%1,%2,%3};"      \
                 : "+f"((c)[0]), "+f"((c)[1]), "+f"((c)[2]), "+f"((c)[3])     \
                 : "r"(a0), "r"(a1), "r"(a2), "r"(a3), "r"(b0), "r"(b1))

#define LDSM_X4(r0, r1, r2, r3, addr)                                         \
    asm volatile("ldmatrix.sync.aligned.m8n8.x4.shared.b16 {%0,%1,%2,%3}, [%4];" \
                 : "=r"(r0), "=r"(r1), "=r"(r2), "=r"(r3) : "r"(addr))

// ---------------- weight prep ----------------
__global__ void prep_w(const float* __restrict__ cw)
{
    int i = blockIdx.x * 256 + threadIdx.x;           // [0, 27*96*16)
    if (i >= 27 * NOC * CIN) return;
    int ci = i % CIN;
    int oc = (i / CIN) % NOC;
    int j  = i / (CIN * NOC);
    float v = cw[(oc * CIN + ci) * 27 + j];
    g_wH[i] = __float2half_rn(v);                     // [j][oc][ci]
    g_w32[(j * CIN + ci) * NOC + oc] = v;             // [j][ci][oc]
}

// ---------------- conv: tensor rows 0-11 + FFMA2 rows 12-15 ----------------
__global__ __launch_bounds__(NTHR, 1)
void conv_mma(const float* __restrict__ x, const float* __restrict__ cb)
{
    extern __shared__ __align__(16) char dsm[];
    __shared__ float cbs[NOC];

    const int tid = threadIdx.x;
    const int wid = tid >> 5;
    const int lid = tid & 31;
    const int wm  = wid & 3;          // tensor m-tile: 3 h-rows each
    const int wn  = wid >> 2;         // tensor n-tile: 32 oc, 0..2

    const int w0 = blockIdx.x * PW;
    const int h0 = blockIdx.y * PH;
    const int zz = blockIdx.z;
    const int t = zz % TT, b = zz / TT;

    const uint32_t sbase = smem_u32(dsm);

    if (tid < NOC) cbs[tid] = __ldg(&cb[tid]);

    // ---- stage xt[3][18][18][24] halves (zero-padded halo) ----
    {
        const float* xb = x + (size_t)b * CIN * TT * HWSZ;
        for (int i = tid; i < 3 * CIN * 18 * 18; i += NTHR) {
            int iw = i % 18;
            int ih = (i / 18) % 18;
            int ci = (i / 324) % CIN;
            int dt = i / (324 * CIN);
            int tg = t - 1 + dt, hh = h0 - 1 + ih, ww = w0 - 1 + iw;
            float v = 0.0f;
            if ((unsigned)tg < TT && (unsigned)hh < HH && (unsigned)ww < WW)
                v = xb[((size_t)ci * TT + tg) * HWSZ + hh * WW + ww];
            *(__half*)(dsm + (((dt * 18 + ih) * 18 + iw) * CIP + ci) * 2)
                = __float2half_rn(v);
        }
    }

    // ---- tensor C fragments (rows 0-11), init with bias ----
    float c[3][4][4];
    {
        const int ocb = wn * 32 + (lid & 3) * 2;
#pragma unroll
        for (int mb = 0; mb < 3; mb++)
#pragma unroll
            for (int nf = 0; nf < 4; nf++) {
                float b0v = cbs[ocb + nf * 8];
                float b1v = cbs[ocb + nf * 8 + 1];
                c[mb][nf][0] = b0v; c[mb][nf][1] = b1v;
                c[mb][nf][2] = b0v; c[mb][nf][3] = b1v;
            }
    }
    // ---- scalar accumulators (rows 12-15, 8 oc per warp) ----
    unsigned long long sacc[2][4];
#pragma unroll
    for (int p = 0; p < 2; p++)
#pragma unroll
        for (int q = 0; q < 4; q++) sacc[p][q] = 0ull;

    // ldmatrix lane addresses
    const int aRow  = (lid & 7) + 8 * ((lid >> 3) & 1);
    const int aKoff = ((lid >> 4) & 1) * 16;
    const uint32_t laneA = sbase + (uint32_t)(aRow * RS + aKoff);
    const uint32_t laneB = sbase + B9_OFF + (uint32_t)((wn * 32 + lid) * RS);
    const int hrow = wm * 3;
    // scalar lane mapping
    const int swl = lid & 15, srh = lid >> 4;
    const int soc0 = wid * 8;

    for (int dt = 0; dt < 3; dt++) {
        __syncthreads();
        // stage B9 (fp16 [9][96][24]) and W32 (f32 [9][16][96]) for this dt
        {
            const float4* src = (const float4*)g_wH;
            for (int i = tid; i < 9 * NOC * 2; i += NTHR) {
                int rr = i >> 1;
                int q  = i & 1;
                float4 v = src[(dt * 9 * NOC + rr) * 2 + q];
                *(float4*)(dsm + B9_OFF + rr * RS + q * 16) = v;
            }
            const float4* s32 = (const float4*)(g_w32 + dt * 9 * CIN * NOC);
            float4* d32 = (float4*)(dsm + W32_OFF);
            for (int i = tid; i < 9 * CIN * NOC / 4; i += NTHR)
                d32[i] = s32[i];
        }
        __syncthreads();

        // ---- tensor: rows hrow..hrow+2 ----
#pragma unroll
        for (int dh = 0; dh < 3; dh++)
#pragma unroll
            for (int dw = 0; dw < 3; dw++) {
                const int j9 = dh * 3 + dw;
                uint32_t b0[4], b1[4];
                {
                    uint32_t ba = laneB + (uint32_t)(j9 * NOC * RS);
                    LDSM_X4(b0[0], b0[1], b0[2], b0[3], ba);
                    LDSM_X4(b1[0], b1[1], b1[2], b1[3], ba + 16u);
                }
#pragma unroll
                for (int mb = 0; mb < 3; mb++) {
                    uint32_t aa = laneA + (uint32_t)
                        ((((dt * 18 + hrow + mb + dh) * 18 + dw)) * RS);
                    uint32_t a0, a1, a2, a3;
                    LDSM_X4(a0, a1, a2, a3, aa);
#pragma unroll
                    for (int nf = 0; nf < 4; nf++)
                        MMA_F16(c[mb][nf], a0, a1, a2, a3, b0[nf], b1[nf]);
                }
            }

        // ---- scalar: rows 12-15, oc soc0..soc0+7, f32 FFMA2 ----
#pragma unroll
        for (int dh = 0; dh < 3; dh++)
#pragma unroll
            for (int dw = 0; dw < 3; dw++) {
                const int j9 = dh * 3 + dw;
                const char* xr0 = dsm +
                    (((dt * 18 + 12 + srh + dh) * 18) + swl + dw) * RS;
                const char* xr1 = xr0 + 2 * 18 * RS;
                uint4 xa = *(const uint4*)xr0;          // px0 ci0..7
                uint4 xb4 = *(const uint4*)(xr0 + 16);  // px0 ci8..15
                uint4 xc = *(const uint4*)xr1;          // px1 ci0..7
                uint4 xd = *(const uint4*)(xr1 + 16);   // px1 ci8..15
                const char* wrow = dsm + W32_OFF
                                 + (size_t)(j9 * CIN) * (NOC * 4) + soc0 * 4;
#pragma unroll
                for (int cp = 0; cp < 8; cp++) {        // ci pairs
                    uint32_t h0 = (cp < 4) ? (&xa.x)[cp] : (&xb4.x)[cp - 4];
                    uint32_t h1 = (cp < 4) ? (&xc.x)[cp] : (&xd.x)[cp - 4];
                    float2 f0 = __half22float2(*(__half2*)&h0);
                    float2 f1 = __half22float2(*(__half2*)&h1);
                    const ulonglong2* we =
                        (const ulonglong2*)(wrow + (2 * cp) * (NOC * 4));
                    const ulonglong2* wo =
                        (const ulonglong2*)(wrow + (2 * cp + 1) * (NOC * 4));
                    ulonglong2 wA = we[0], wB = we[1];  // ci even: 4 pairs
                    ulonglong2 wC = wo[0], wD = wo[1];  // ci odd : 4 pairs
                    unsigned long long x0e = dup2(f0.x), x0o = dup2(f0.y);
                    unsigned long long x1e = dup2(f1.x), x1o = dup2(f1.y);
                    fma2(sacc[0][0], x0e, wA.x); fma2(sacc[0][1], x0e, wA.y);
                    fma2(sacc[0][2], x0e, wB.x); fma2(sacc[0][3], x0e, wB.y);
                    fma2(sacc[0][0], x0o, wC.x); fma2(sacc[0][1], x0o, wC.y);
                    fma2(sacc[0][2], x0o, wD.x); fma2(sacc[0][3], x0o, wD.y);
                    fma2(sacc[1][0], x1e, wA.x); fma2(sacc[1][1], x1e, wA.y);
                    fma2(sacc[1][2], x1e, wB.x); fma2(sacc[1][3], x1e, wB.y);
                    fma2(sacc[1][0], x1o, wC.x); fma2(sacc[1][1], x1o, wC.y);
                    fma2(sacc[1][2], x1o, wD.x); fma2(sacc[1][3], x1o, wD.y);
                }
            }
    }

    // ---- tensor epilogue: rows 0-11 ----
    {
        const int r  = lid >> 2;
        const int wA = w0 + r;
        const size_t tbase = (size_t)t * HWSZ;
#pragma unroll
        for (int mb = 0; mb < 3; mb++) {
            const int hA = h0 + hrow + mb;
            const size_t rowoff = tbase + (size_t)hA * WW;
#pragma unroll
            for (int nf = 0; nf < 4; nf++) {
                const int oc0 = wn * 32 + nf * 8 + (lid & 3) * 2;
                const int g = oc0 >> 4;
                const bool th = (g == 0) || (g == 5);
                float v0 = c[mb][nf][0], v1 = c[mb][nf][1];
                float v2 = c[mb][nf][2], v3 = c[mb][nf][3];
                v0 = th ? tanhfst(v0) : sigf(v0);
                v1 = th ? tanhfst(v1) : sigf(v1);
                v2 = th ? tanhfst(v2) : sigf(v2);
                v3 = th ? tanhfst(v3) : sigf(v3);
                float* p0 = g_gates + ((size_t)(g * BB + b) * CG + (oc0 & 15))
                            * (TT * HWSZ) + rowoff + wA;
                float* p1 = g_gates + ((size_t)(g * BB + b) * CG + ((oc0 + 1) & 15))
                            * (TT * HWSZ) + rowoff + wA;
                p0[0] = v0;  p1[0] = v1;
                p0[8] = v2;  p1[8] = v3;
            }
        }
    }
    // ---- scalar epilogue: rows 12-15 ----
    {
        const size_t tbase = (size_t)t * HWSZ;
#pragma unroll
        for (int p = 0; p < 2; p++) {
            const int row = 12 + srh + 2 * p;
            const size_t rowoff = tbase + (size_t)(h0 + row) * WW + (w0 + swl);
#pragma unroll
            for (int q = 0; q < 4; q++) {
                const int oc = soc0 + 2 * q;
                float v0, v1;
                unpack2(sacc[p][q], v0, v1);
                v0 += cbs[oc]; v1 += cbs[oc + 1];
                const int g = oc >> 4;
                const bool th = (g == 0) || (g == 5);
                v0 = th ? tanhfst(v0) : sigf(v0);
                v1 = th ? tanhfst(v1) : sigf(v1);
                g_gates[((size_t)(g * BB + b) * CG + (oc & 15)) * (TT * HWSZ)
                        + rowoff] = v0;
                g_gates[((size_t)(g * BB + b) * CG + ((oc + 1) & 15)) * (TT * HWSZ)
                        + rowoff] = v1;
            }
        }
    }
}

// ---------------- SRU scan (HBM-bound @80%, unchanged) ----------------
__global__ __launch_bounds__(256)
void sru_scan_kernel(float* __restrict__ out)
{
    const int tid = blockIdx.x * blockDim.x + threadIdx.x;
    const int hw = tid & (HWSZ - 1);
    const int bc = tid >> 14;
    const int c  = bc & 15;
    const int b  = bc >> 4;

    const size_t GSZ  = (size_t)BB * CG * TT * HWSZ;
    const size_t base = (((size_t)b * CG + c) * TT) * HWSZ + hw;

    const float* WX  = g_gates + 0 * GSZ + base;
    const float* FT  = g_gates + 1 * GSZ + base;
    const float* FT2 = g_gates + 2 * GSZ + base;
    const float* RT  = g_gates + 3 * GSZ + base;
    const float* RT2 = g_gates + 4 * GSZ + base;
    const float* XX  = g_gates + 5 * GSZ + base;
    float* o = out + base;

    float htl[TT];
    {
        float f = FT[0];
        float C = 1.0f - f;
        float r = RT[0];
        htl[0] = r * C + (1.0f - r) * XX[0];
#pragma unroll
        for (int t = 1; t < TT; t++) {
            size_t idx = (size_t)t * HWSZ;
            f = FT[idx];
            C = f * C + (1.0f - f) * WX[idx];
            float r2 = RT[idx];
            htl[t] = r2 * C + (1.0f - r2) * XX[idx];
        }
    }
    {
        size_t idx = (size_t)(TT - 1) * HWSZ;
        float f = FT2[idx];
        float C = 1.0f - f;
        float r = RT2[idx];
        o[idx] = htl[TT - 1] + r * C + (1.0f - r) * XX[idx];
#pragma unroll
        for (int t = TT - 2; t >= 0; t--) {
            idx = (size_t)t * HWSZ;
            f = FT2[idx];
            C = f * C + (1.0f - f) * WX[idx];
            float r2 = RT2[idx];
            o[idx] = htl[t] + r2 * C + (1.0f - r2) * XX[idx];
        }
    }
}

extern "C" void kernel_launch(void* const* d_in, const int* in_sizes, int n_in,
                              void* d_out, int out_size)
{
    const float* x  = (const float*)d_in[0];   // [2,16,31,128,128]
    const float* cw = (const float*)d_in[1];   // [96,16,3,3,3]
    const float* cb = (const float*)d_in[2];   // [96]
    float* out = (float*)d_out;

    cudaFuncSetAttribute(conv_mma, cudaFuncAttributeMaxDynamicSharedMemorySize,
                         SMEM_DYN);

    prep_w<<<(27 * NOC * CIN + 255) / 256, 256>>>(cw);

    dim3 grd(WW / PW, HH / PH, BB * TT);       // (8, 8, 62) = 3968 CTAs
    conv_mma<<<grd, NTHR, SMEM_DYN>>>(x, cb);

    int n = BB * CG * HWSZ;
    sru_scan_kernel<<<n / 256, 256>>>(out);
}

// round 10
// speedup vs baseline: 1.3460x; 1.3460x over previous
#include <cuda_runtime.h>
#include <cuda_fp16.h>
#include <math.h>
#include <stdint.h>

#define BB   2
#define CIN  16
#define NG   6
#define CG   16
#define NOC  96
#define TT   31
#define HH   128
#define WW   128
#define HWSZ (HH*WW)

// CTA: 8h x 16w output pixels = 4x8 = 32 Winograd tiles (2x2 out each)
#define NTHR 384          // 12 warps: wm = wid&1 (16 tiles), wn = wid>>1 (16 oc)

// smem layout (dynamic):
//   halo [3dt][10][18][16ci] fp16 : 17280 B
//   V^   [16pt][32 tile][56 k]    : 16*32*112 = 57344 B  (48 real k)
//   W^   2 bufs [96 oc][56 k]     : 2*10752 B
#define HALO_OFF 0
#define HALO_BYTES (3*10*18*16*2)
#define VS_OFF   HALO_BYTES
#define VROW     112
#define VS_BYTES (16*32*VROW)
#define WS_OFF   (VS_OFF + VS_BYTES)
#define WS_BYTES (96*VROW)
#define SMEM_DYN (WS_OFF + 2*WS_BYTES)   // 96128

// gates scratch [g][b][c][t][h][w]
__device__ float g_gates[(size_t)NG * BB * CG * TT * HWSZ];
// Winograd weights U = G g G^T : [pt=16][oc=96][56 k-pad] fp16 (k = dt*16+ci)
__device__ __align__(16) __half g_wW[16 * NOC * 56];

// ---------------- helpers ----------------
__device__ __forceinline__ uint32_t smem_u32(const void* p) {
    uint32_t a;
    asm("{ .reg .u64 t; cvta.to.shared.u64 t, %1; cvt.u32.u64 %0, t; }"
        : "=r"(a) : "l"(p));
    return a;
}
__device__ __forceinline__ float ex2f(float z) {
    float r; asm("ex2.approx.f32 %0, %1;" : "=f"(r) : "f"(z)); return r;
}
__device__ __forceinline__ float rcpn(float d) {
    float r; asm("rcp.approx.f32 %0, %1;" : "=f"(r) : "f"(d));
    return r * fmaf(-d, r, 2.0f);
}
__device__ __forceinline__ float sigf(float v) {
    v = fminf(fmaxf(v, -80.f), 80.f);
    return rcpn(1.0f + ex2f(-1.442695041f * v));
}
__device__ __forceinline__ float tanhfst(float v) {
    v = fminf(fmaxf(v, -40.f), 40.f);
    return fmaf(2.0f, rcpn(1.0f + ex2f(-2.885390082f * v)), -1.0f);
}
__device__ __forceinline__ float2 f2add(float2 a, float2 b) {
    return make_float2(a.x + b.x, a.y + b.y);
}
__device__ __forceinline__ float2 f2sub(float2 a, float2 b) {
    return make_float2(a.x - b.x, a.y - b.y);
}

#define MMA_F16(c, a0, a1, a2, a3, b0, b1)                                    \
    asm volatile("mma.sync.aligned.m16n8k16.row.col.f32.f16.f16.f32 "         \
                 "{%0,%1,%2,%3}, {%4,%5,%6,%7}, {%8,%9}, {%0,%1,%2,%3};"      \
                 : "+f"((c)[0]), "+f"((c)[1]), "+f"((c)[2]), "+f"((c)[3])     \
                 : "r"(a0), "r"(a1), "r"(a2), "r"(a3), "r"(b0), "r"(b1))

#define LDSM_X4(r0, r1, r2, r3, addr)                                         \
    asm volatile("ldmatrix.sync.aligned.m8n8.x4.shared.b16 {%0,%1,%2,%3}, [%4];" \
                 : "=r"(r0), "=r"(r1), "=r"(r2), "=r"(r3) : "r"(addr))

// ---------------- weight prep: U = G g G^T, fp16, [pt][oc][56] ----------------
__global__ void prep_w(const float* __restrict__ cw)
{
    int idx = blockIdx.x * 256 + threadIdx.x;        // [0, 16*96*48)
    if (idx >= 16 * NOC * 48) return;
    int k  = idx % 48;
    int oc = (idx / 48) % NOC;
    int pt = idx / (48 * NOC);
    int ci = k & 15, dt = k >> 4;
    int xi = pt >> 2, nu = pt & 3;

    const float Gm[4][3] = {{1.f,0.f,0.f},{0.5f,0.5f,0.5f},
                            {0.5f,-0.5f,0.5f},{0.f,0.f,1.f}};
    const float* g = cw + ((size_t)oc * CIN + ci) * 27 + dt * 9;
    float u = 0.f;
#pragma unroll
    for (int dh = 0; dh < 3; dh++)
#pragma unroll
        for (int dw = 0; dw < 3; dw++)
            u += Gm[xi][dh] * Gm[nu][dw] * g[dh * 3 + dw];
    g_wW[((size_t)pt * NOC + oc) * 56 + k] = __float2half_rn(u);
}

// ---------------- conv: Winograd F(2x2,3x3), fp16 mma ----------------
__global__ __launch_bounds__(NTHR, 2)
void conv_wino(const float* __restrict__ x, const float* __restrict__ cb)
{
    extern __shared__ __align__(16) char dsm[];
    __shared__ float cbs[NOC];

    const int tid = threadIdx.x;
    const int wid = tid >> 5;
    const int lid = tid & 31;
    const int wm  = wid & 1;          // m-group: 16 tiles
    const int wn  = wid >> 1;         // n-group: 16 oc (== gate index!)

    const int w0 = blockIdx.x * 16;
    const int h0 = blockIdx.y * 8;
    const int zz = blockIdx.z;
    const int t = zz % TT, b = zz / TT;

    const uint32_t sbase = smem_u32(dsm);

    if (tid < NOC) cbs[tid] = __ldg(&cb[tid]);

    // ---- stage halo [3][10][18][16] fp16 (h0-1..h0+8, w0-1..w0+16) ----
    {
        const float* xb = x + (size_t)b * CIN * TT * HWSZ;
        for (int i = tid; i < 3 * 10 * 18 * CIN; i += NTHR) {
            int iw  = i % 18;
            int ih  = (i / 18) % 10;
            int ci  = (i / 180) % CIN;
            int dtt = i / 2880;
            int tg = t - 1 + dtt, hh = h0 - 1 + ih, ww = w0 - 1 + iw;
            float v = 0.0f;
            if ((unsigned)tg < TT && (unsigned)hh < HH && (unsigned)ww < WW)
                v = xb[((size_t)ci * TT + tg) * HWSZ + hh * WW + ww];
            *(__half*)(dsm + (((dtt * 10 + ih) * 18 + iw) * 16 + ci) * 2)
                = __float2half_rn(v);
        }
    }
    // ---- stage W^[0] into buf0 ----
    {
        const float4* ws = (const float4*)g_wW;
        float4* wd = (float4*)(dsm + WS_OFF);
        for (int i = tid; i < WS_BYTES / 16; i += NTHR) wd[i] = ws[i];
    }
    __syncthreads();

    // ---- input transform: V^[pt][tile][k], all 16 points, f32 math ----
    // item = (tile, dt, cipair): 32*3*8 = 768, 2 per thread
#pragma unroll
    for (int rep = 0; rep < 2; rep++) {
        const int it  = tid + rep * NTHR;
        const int cp  = it & 7;
        const int tl  = (it >> 3) & 31;
        const int dtt = it >> 8;
        const int th_ = tl >> 3, tw_ = tl & 7;

        float2 d[4][4];
#pragma unroll
        for (int i = 0; i < 4; i++)
#pragma unroll
            for (int j = 0; j < 4; j++) {
                uint32_t h2 = *(const uint32_t*)(dsm +
                    (((dtt * 10 + 2 * th_ + i) * 18 + 2 * tw_ + j) * 16
                     + cp * 2) * 2);
                d[i][j] = __half22float2(*(const __half2*)&h2);
            }
        // rows: B^T d
        float2 tr[4][4];
#pragma unroll
        for (int j = 0; j < 4; j++) {
            tr[0][j] = f2sub(d[0][j], d[2][j]);
            tr[1][j] = f2add(d[1][j], d[2][j]);
            tr[2][j] = f2sub(d[2][j], d[1][j]);
            tr[3][j] = f2sub(d[1][j], d[3][j]);
        }
        // cols: (B^T d) B
#pragma unroll
        for (int i = 0; i < 4; i++) {
            float2 v0 = f2sub(tr[i][0], tr[i][2]);
            float2 v1 = f2add(tr[i][1], tr[i][2]);
            float2 v2 = f2sub(tr[i][2], tr[i][1]);
            float2 v3 = f2sub(tr[i][1], tr[i][3]);
            float2 vv[4] = {v0, v1, v2, v3};
#pragma unroll
            for (int j = 0; j < 4; j++) {
                __half2 hv = __float22half2_rn(vv[j]);
                *(__half2*)(dsm + VS_OFF + ((i * 4 + j) * 32 + tl) * VROW
                            + dtt * 32 + cp * 4) = hv;
            }
        }
    }

    // ---- Y accumulators (2x2 out px per tile), init with bias ----
    // lane owns tiles {wm*16 + r, +8}, ocs wn*16 + {2q,2q+1,8+2q,8+2q+1}
    float y[2][2][2][2][2];   // [ti][nf][par][py][px]
    {
        const int q = lid & 3;
#pragma unroll
        for (int nf = 0; nf < 2; nf++)
#pragma unroll
            for (int par = 0; par < 2; par++) {
                float bv = cbs[wn * 16 + nf * 8 + q * 2 + par];
#pragma unroll
                for (int ti = 0; ti < 2; ti++) {
                    y[ti][nf][par][0][0] = bv; y[ti][nf][par][0][1] = bv;
                    y[ti][nf][par][1][0] = bv; y[ti][nf][par][1][1] = bv;
                }
            }
    }
    __syncthreads();

    // ldmatrix lane addresses
    const int aRow  = (lid & 7) + 8 * ((lid >> 3) & 1);
    const int aKoff = ((lid >> 4) & 1) * 16;
    const uint32_t laneA = sbase + VS_OFF
        + (uint32_t)((wm * 16 + aRow) * VROW + aKoff);
    const uint32_t laneB = sbase + WS_OFF
        + (uint32_t)((wn * 16 + (lid & 15)) * VROW + ((lid >> 4) & 1) * 16);

    const int AT[2][4] = {{1, 1, 1, 0}, {0, 1, -1, -1}};

#pragma unroll
    for (int pt = 0; pt < 16; pt++) {
        float c[2][4];
        c[0][0]=0;c[0][1]=0;c[0][2]=0;c[0][3]=0;
        c[1][0]=0;c[1][1]=0;c[1][2]=0;c[1][3]=0;

        const uint32_t va = laneA + (uint32_t)(pt * 32 * VROW);
        const uint32_t wa = laneB + (uint32_t)((pt & 1) * WS_BYTES);
#pragma unroll
        for (int kk = 0; kk < 3; kk++) {
            uint32_t a0, a1, a2, a3, r0, r1, r2, r3;
            LDSM_X4(a0, a1, a2, a3, va + kk * 32);
            LDSM_X4(r0, r1, r2, r3, wa + kk * 32);
            MMA_F16(c[0], a0, a1, a2, a3, r0, r2);
            MMA_F16(c[1], a0, a1, a2, a3, r1, r3);
        }

        // stage next W^ into the other buffer
        if (pt < 15) {
            const float4* ws = (const float4*)(g_wW + (size_t)(pt + 1) * NOC * 56);
            float4* wd = (float4*)(dsm + WS_OFF + ((pt + 1) & 1) * WS_BYTES);
            for (int i = tid; i < WS_BYTES / 16; i += NTHR) wd[i] = ws[i];
        }

        // accumulate into Y with A^T coeffs (compile-time after unroll)
        const int xi = pt >> 2, nu = pt & 3;
#pragma unroll
        for (int ti = 0; ti < 2; ti++)
#pragma unroll
            for (int nf = 0; nf < 2; nf++)
#pragma unroll
                for (int par = 0; par < 2; par++) {
                    float v = c[nf][par + 2 * ti];
#pragma unroll
                    for (int py = 0; py < 2; py++) {
                        int ay = AT[py][xi];
                        if (ay == 0) continue;
#pragma unroll
                        for (int px = 0; px < 2; px++) {
                            int ax = AT[px][nu];
                            if (ax == 0) continue;
                            if (ay * ax > 0) y[ti][nf][par][py][px] += v;
                            else            y[ti][nf][par][py][px] -= v;
                        }
                    }
                }
        __syncthreads();
    }

    // ---- epilogue: activate + store 2x2 px per (tile, oc) ----
    {
        const int r = lid >> 2, q = lid & 3;
        const bool th = (wn == 0) || (wn == 5);
        const size_t tbase = (size_t)t * HWSZ;
#pragma unroll
        for (int ti = 0; ti < 2; ti++) {
            const int tl  = wm * 16 + r + 8 * ti;
            const int hA  = h0 + 2 * (tl >> 3);
            const int wA  = w0 + 2 * (tl & 7);
#pragma unroll
            for (int nf = 0; nf < 2; nf++)
#pragma unroll
                for (int par = 0; par < 2; par++) {
                    const int ocl = nf * 8 + q * 2 + par;
                    float* bp = g_gates
                        + ((size_t)(wn * BB + b) * CG + ocl) * (TT * HWSZ)
                        + tbase;
#pragma unroll
                    for (int py = 0; py < 2; py++) {
                        float v0 = y[ti][nf][par][py][0];
                        float v1 = y[ti][nf][par][py][1];
                        v0 = th ? tanhfst(v0) : sigf(v0);
                        v1 = th ? tanhfst(v1) : sigf(v1);
                        *(float2*)(bp + (size_t)(hA + py) * WW + wA)
                            = make_float2(v0, v1);
                    }
                }
        }
    }
}

// ---------------- SRU scan (HBM-bound @80%, unchanged) ----------------
__global__ __launch_bounds__(256)
void sru_scan_kernel(float* __restrict__ out)
{
    const int tid = blockIdx.x * blockDim.x + threadIdx.x;
    const int hw = tid & (HWSZ - 1);
    const int bc = tid >> 14;
    const int c  = bc & 15;
    const int b  = bc >> 4;

    const size_t GSZ  = (size_t)BB * CG * TT * HWSZ;
    const size_t base = (((size_t)b * CG + c) * TT) * HWSZ + hw;

    const float* WX  = g_gates + 0 * GSZ + base;
    const float* FT  = g_gates + 1 * GSZ + base;
    const float* FT2 = g_gates + 2 * GSZ + base;
    const float* RT  = g_gates + 3 * GSZ + base;
    const float* RT2 = g_gates + 4 * GSZ + base;
    const float* XX  = g_gates + 5 * GSZ + base;
    float* o = out + base;

    float htl[TT];
    {
        float f = FT[0];
        float C = 1.0f - f;
        float r = RT[0];
        htl[0] = r * C + (1.0f - r) * XX[0];
#pragma unroll
        for (int t = 1; t < TT; t++) {
            size_t idx = (size_t)t * HWSZ;
            f = FT[idx];
            C = f * C + (1.0f - f) * WX[idx];
            float r2 = RT[idx];
            htl[t] = r2 * C + (1.0f - r2) * XX[idx];
        }
    }
    {
        size_t idx = (size_t)(TT - 1) * HWSZ;
        float f = FT2[idx];
        float C = 1.0f - f;
        float r = RT2[idx];
        o[idx] = htl[TT - 1] + r * C + (1.0f - r) * XX[idx];
#pragma unroll
        for (int t = TT - 2; t >= 0; t--) {
            idx = (size_t)t * HWSZ;
            f = FT2[idx];
            C = f * C + (1.0f - f) * WX[idx];
            float r2 = RT2[idx];
            o[idx] = htl[t] + r2 * C + (1.0f - r2) * XX[idx];
        }
    }
}

extern "C" void kernel_launch(void* const* d_in, const int* in_sizes, int n_in,
                              void* d_out, int out_size)
{
    const float* x  = (const float*)d_in[0];   // [2,16,31,128,128]
    const float* cw = (const float*)d_in[1];   // [96,16,3,3,3]
    const float* cb = (const float*)d_in[2];   // [96]
    float* out = (float*)d_out;

    cudaFuncSetAttribute(conv_wino, cudaFuncAttributeMaxDynamicSharedMemorySize,
                         SMEM_DYN);

    prep_w<<<(16 * NOC * 48 + 255) / 256, 256>>>(cw);

    dim3 grd(WW / 16, HH / 8, BB * TT);        // (8, 16, 62) = 7936 CTAs
    conv_wino<<<grd, NTHR, SMEM_DYN>>>(x, cb);

    int n = BB * CG * HWSZ;
    sru_scan_kernel<<<n / 256, 256>>>(out);
}

// round 11
// speedup vs baseline: 1.8869x; 1.4019x over previous
#include <cuda_runtime.h>
#include <cuda_fp16.h>
#include <math.h>
#include <stdint.h>

#define BB   2
#define CIN  16
#define NG   6
#define CG   16
#define NOC  96
#define TT   31
#define HH   128
#define WW   128
#define HWSZ (HH*WW)

// CTA: 8h x 16w output pixels = 4x8 = 32 Winograd tiles (2x2 out each)
#define NTHR 384          // 12 warps: wm = wid&1 (16 tiles), wn = wid>>1 (16 oc)

// smem layout (dynamic):
//   halo [3dt][10][18][16ci] fp16 : 17280 B
//   V^   [16pt][32 tile][56 k]    : 57344 B (48 real k)
#define HALO_BYTES (3*10*18*16*2)
#define VS_OFF   HALO_BYTES
#define VROW     112
#define VS_BYTES (16*32*VROW)
#define SMEM_DYN (VS_OFF + VS_BYTES)   // 74624

// gates scratch [g][b][c][t][h][w]
__device__ float g_gates[(size_t)NG * BB * CG * TT * HWSZ];
// Winograd weights U = G g G^T : [pt=16][oc=96][48 k] fp16 (k = dt*16+ci)
__device__ __align__(16) __half g_wW[16 * NOC * 48];

// ---------------- helpers ----------------
__device__ __forceinline__ uint32_t smem_u32(const void* p) {
    uint32_t a;
    asm("{ .reg .u64 t; cvta.to.shared.u64 t, %1; cvt.u32.u64 %0, t; }"
        : "=r"(a) : "l"(p));
    return a;
}
__device__ __forceinline__ float ex2f(float z) {
    float r; asm("ex2.approx.f32 %0, %1;" : "=f"(r) : "f"(z)); return r;
}
__device__ __forceinline__ float rcpn(float d) {
    float r; asm("rcp.approx.f32 %0, %1;" : "=f"(r) : "f"(d));
    return r * fmaf(-d, r, 2.0f);
}
__device__ __forceinline__ float sigf(float v) {
    v = fminf(fmaxf(v, -80.f), 80.f);
    return rcpn(1.0f + ex2f(-1.442695041f * v));
}
__device__ __forceinline__ float tanhfst(float v) {
    v = fminf(fmaxf(v, -40.f), 40.f);
    return fmaf(2.0f, rcpn(1.0f + ex2f(-2.885390082f * v)), -1.0f);
}
__device__ __forceinline__ float2 f2add(float2 a, float2 b) {
    return make_float2(a.x + b.x, a.y + b.y);
}
__device__ __forceinline__ float2 f2sub(float2 a, float2 b) {
    return make_float2(a.x - b.x, a.y - b.y);
}

#define MMA_F16(c, a0, a1, a2, a3, b0, b1)                                    \
    asm volatile("mma.sync.aligned.m16n8k16.row.col.f32.f16.f16.f32 "         \
                 "{%0,%1,%2,%3}, {%4,%5,%6,%7}, {%8,%9}, {%0,%1,%2,%3};"      \
                 : "+f"((c)[0]), "+f"((c)[1]), "+f"((c)[2]), "+f"((c)[3])     \
                 : "r"(a0), "r"(a1), "r"(a2), "r"(a3), "r"(b0), "r"(b1))

#define LDSM_X4(r0, r1, r2, r3, addr)                                         \
    asm volatile("ldmatrix.sync.aligned.m8n8.x4.shared.b16 {%0,%1,%2,%3}, [%4];" \
                 : "=r"(r0), "=r"(r1), "=r"(r2), "=r"(r3) : "r"(addr))

// ---------------- weight prep: U = G g G^T, fp16, [pt][oc][48] ----------------
__global__ void prep_w(const float* __restrict__ cw)
{
    int idx = blockIdx.x * 256 + threadIdx.x;        // [0, 16*96*48)
    if (idx >= 16 * NOC * 48) return;
    int k  = idx % 48;
    int oc = (idx / 48) % NOC;
    int pt = idx / (48 * NOC);
    int ci = k & 15, dt = k >> 4;
    int xi = pt >> 2, nu = pt & 3;

    const float Gm[4][3] = {{1.f,0.f,0.f},{0.5f,0.5f,0.5f},
                            {0.5f,-0.5f,0.5f},{0.f,0.f,1.f}};
    const float* g = cw + ((size_t)oc * CIN + ci) * 27 + dt * 9;
    float u = 0.f;
#pragma unroll
    for (int dh = 0; dh < 3; dh++)
#pragma unroll
        for (int dw = 0; dw < 3; dw++)
            u += Gm[xi][dh] * Gm[nu][dw] * g[dh * 3 + dw];
    g_wW[((size_t)pt * NOC + oc) * 48 + k] = __float2half_rn(u);
}

// ---------------- conv: Winograd F(2x2,3x3), fp16 mma, barrier-free loop ----
__global__ __launch_bounds__(NTHR, 2)
void conv_wino(const float* __restrict__ x, const float* __restrict__ cb)
{
    extern __shared__ __align__(16) char dsm[];
    __shared__ float cbs[NOC];

    const int tid = threadIdx.x;
    const int wid = tid >> 5;
    const int lid = tid & 31;
    const int wm  = wid & 1;          // m-group: 16 tiles
    const int wn  = wid >> 1;         // n-group: 16 oc (== gate index!)

    const int w0 = blockIdx.x * 16;
    const int h0 = blockIdx.y * 8;
    const int zz = blockIdx.z;
    const int t = zz % TT, b = zz / TT;

    const uint32_t sbase = smem_u32(dsm);

    if (tid < NOC) cbs[tid] = __ldg(&cb[tid]);

    // ---- stage halo [3][10][18][16] fp16 (h0-1..h0+8, w0-1..w0+16) ----
    {
        const float* xb = x + (size_t)b * CIN * TT * HWSZ;
        for (int i = tid; i < 3 * 10 * 18 * CIN; i += NTHR) {
            int iw  = i % 18;
            int ih  = (i / 18) % 10;
            int ci  = (i / 180) % CIN;
            int dtt = i / 2880;
            int tg = t - 1 + dtt, hh = h0 - 1 + ih, ww = w0 - 1 + iw;
            float v = 0.0f;
            if ((unsigned)tg < TT && (unsigned)hh < HH && (unsigned)ww < WW)
                v = xb[((size_t)ci * TT + tg) * HWSZ + hh * WW + ww];
            *(__half*)(dsm + (((dtt * 10 + ih) * 18 + iw) * 16 + ci) * 2)
                = __float2half_rn(v);
        }
    }
    __syncthreads();

    // ---- input transform: V^[pt][tile][k], f32 math ----
#pragma unroll
    for (int rep = 0; rep < 2; rep++) {
        const int it  = tid + rep * NTHR;
        const int cp  = it & 7;
        const int tl  = (it >> 3) & 31;
        const int dtt = it >> 8;
        const int th_ = tl >> 3, tw_ = tl & 7;

        float2 d[4][4];
#pragma unroll
        for (int i = 0; i < 4; i++)
#pragma unroll
            for (int j = 0; j < 4; j++) {
                uint32_t h2 = *(const uint32_t*)(dsm +
                    (((dtt * 10 + 2 * th_ + i) * 18 + 2 * tw_ + j) * 16
                     + cp * 2) * 2);
                d[i][j] = __half22float2(*(const __half2*)&h2);
            }
        float2 tr[4][4];
#pragma unroll
        for (int j = 0; j < 4; j++) {
            tr[0][j] = f2sub(d[0][j], d[2][j]);
            tr[1][j] = f2add(d[1][j], d[2][j]);
            tr[2][j] = f2sub(d[2][j], d[1][j]);
            tr[3][j] = f2sub(d[1][j], d[3][j]);
        }
#pragma unroll
        for (int i = 0; i < 4; i++) {
            float2 v0 = f2sub(tr[i][0], tr[i][2]);
            float2 v1 = f2add(tr[i][1], tr[i][2]);
            float2 v2 = f2sub(tr[i][2], tr[i][1]);
            float2 v3 = f2sub(tr[i][1], tr[i][3]);
            float2 vv[4] = {v0, v1, v2, v3};
#pragma unroll
            for (int j = 0; j < 4; j++) {
                __half2 hv = __float22half2_rn(vv[j]);
                *(__half2*)(dsm + VS_OFF + ((i * 4 + j) * 32 + tl) * VROW
                            + dtt * 32 + cp * 4) = hv;
            }
        }
    }

    // ---- Y accumulators (2x2 out px per tile), init with bias ----
    float y[2][2][2][2][2];   // [ti][nf][par][py][px]
    {
        const int q = lid & 3;
#pragma unroll
        for (int nf = 0; nf < 2; nf++)
#pragma unroll
            for (int par = 0; par < 2; par++) {
                float bv = cbs[wn * 16 + nf * 8 + q * 2 + par];
#pragma unroll
                for (int ti = 0; ti < 2; ti++) {
                    y[ti][nf][par][0][0] = bv; y[ti][nf][par][0][1] = bv;
                    y[ti][nf][par][1][0] = bv; y[ti][nf][par][1][1] = bv;
                }
            }
    }
    __syncthreads();   // V^ fully built; loop below is barrier-free

    // A fragment lane address (LDSM from V^)
    const int aRow  = (lid & 7) + 8 * ((lid >> 3) & 1);
    const int aKoff = ((lid >> 4) & 1) * 16;
    const uint32_t laneA = sbase + VS_OFF
        + (uint32_t)((wm * 16 + aRow) * VROW + aKoff);

    // B fragment lane gmem pointers: n0 = wn*16 + lid>>2 (nf0), n1 = n0+8 (nf1)
    // b0 @ k=(lid&3)*2 + kk*16 ; b1 @ +8
    const __half* wrow0 = g_wW + (size_t)(wn * 16 + (lid >> 2)) * 48
                        + (lid & 3) * 2;
    const __half* wrow1 = wrow0 + 8 * 48;

    const int AT[2][4] = {{1, 1, 1, 0}, {0, 1, -1, -1}};

#pragma unroll
    for (int pt = 0; pt < 16; pt++) {
        float c[2][4];
        c[0][0]=0;c[0][1]=0;c[0][2]=0;c[0][3]=0;
        c[1][0]=0;c[1][1]=0;c[1][2]=0;c[1][3]=0;

        const uint32_t va = laneA + (uint32_t)(pt * 32 * VROW);
        const __half* w0p = wrow0 + (size_t)pt * NOC * 48;
        const __half* w1p = wrow1 + (size_t)pt * NOC * 48;
#pragma unroll
        for (int kk = 0; kk < 3; kk++) {
            uint32_t a0, a1, a2, a3;
            LDSM_X4(a0, a1, a2, a3, va + kk * 32);
            uint32_t b00 = __ldg((const uint32_t*)(w0p + kk * 16));
            uint32_t b01 = __ldg((const uint32_t*)(w0p + kk * 16 + 8));
            uint32_t b10 = __ldg((const uint32_t*)(w1p + kk * 16));
            uint32_t b11 = __ldg((const uint32_t*)(w1p + kk * 16 + 8));
            MMA_F16(c[0], a0, a1, a2, a3, b00, b01);
            MMA_F16(c[1], a0, a1, a2, a3, b10, b11);
        }

        // accumulate into Y with A^T coeffs (compile-time after unroll)
        const int xi = pt >> 2, nu = pt & 3;
#pragma unroll
        for (int ti = 0; ti < 2; ti++)
#pragma unroll
            for (int nf = 0; nf < 2; nf++)
#pragma unroll
                for (int par = 0; par < 2; par++) {
                    float v = c[nf][par + 2 * ti];
#pragma unroll
                    for (int py = 0; py < 2; py++) {
                        int ay = AT[py][xi];
                        if (ay == 0) continue;
#pragma unroll
                        for (int px = 0; px < 2; px++) {
                            int ax = AT[px][nu];
                            if (ax == 0) continue;
                            if (ay * ax > 0) y[ti][nf][par][py][px] += v;
                            else            y[ti][nf][par][py][px] -= v;
                        }
                    }
                }
    }

    // ---- epilogue: activate + store 2x2 px per (tile, oc) ----
    {
        const int r = lid >> 2, q = lid & 3;
        const bool th = (wn == 0) || (wn == 5);
        const size_t tbase = (size_t)t * HWSZ;
#pragma unroll
        for (int ti = 0; ti < 2; ti++) {
            const int tl  = wm * 16 + r + 8 * ti;
            const int hA  = h0 + 2 * (tl >> 3);
            const int wA  = w0 + 2 * (tl & 7);
#pragma unroll
            for (int nf = 0; nf < 2; nf++)
#pragma unroll
                for (int par = 0; par < 2; par++) {
                    const int ocl = nf * 8 + q * 2 + par;
                    float* bp = g_gates
                        + ((size_t)(wn * BB + b) * CG + ocl) * (TT * HWSZ)
                        + tbase;
#pragma unroll
                    for (int py = 0; py < 2; py++) {
                        float v0 = y[ti][nf][par][py][0];
                        float v1 = y[ti][nf][par][py][1];
                        v0 = th ? tanhfst(v0) : sigf(v0);
                        v1 = th ? tanhfst(v1) : sigf(v1);
                        *(float2*)(bp + (size_t)(hA + py) * WW + wA)
                            = make_float2(v0, v1);
                    }
                }
        }
    }
}

// ---------------- SRU scan (HBM-bound @80%, unchanged) ----------------
__global__ __launch_bounds__(256)
void sru_scan_kernel(float* __restrict__ out)
{
    const int tid = blockIdx.x * blockDim.x + threadIdx.x;
    const int hw = tid & (HWSZ - 1);
    const int bc = tid >> 14;
    const int c  = bc & 15;
    const int b  = bc >> 4;

    const size_t GSZ  = (size_t)BB * CG * TT * HWSZ;
    const size_t base = (((size_t)b * CG + c) * TT) * HWSZ + hw;

    const float* WX  = g_gates + 0 * GSZ + base;
    const float* FT  = g_gates + 1 * GSZ + base;
    const float* FT2 = g_gates + 2 * GSZ + base;
    const float* RT  = g_gates + 3 * GSZ + base;
    const float* RT2 = g_gates + 4 * GSZ + base;
    const float* XX  = g_gates + 5 * GSZ + base;
    float* o = out + base;

    float htl[TT];
    {
        float f = FT[0];
        float C = 1.0f - f;
        float r = RT[0];
        htl[0] = r * C + (1.0f - r) * XX[0];
#pragma unroll
        for (int t = 1; t < TT; t++) {
            size_t idx = (size_t)t * HWSZ;
            f = FT[idx];
            C = f * C + (1.0f - f) * WX[idx];
            float r2 = RT[idx];
            htl[t] = r2 * C + (1.0f - r2) * XX[idx];
        }
    }
    {
        size_t idx = (size_t)(TT - 1) * HWSZ;
        float f = FT2[idx];
        float C = 1.0f - f;
        float r = RT2[idx];
        o[idx] = htl[TT - 1] + r * C + (1.0f - r) * XX[idx];
#pragma unroll
        for (int t = TT - 2; t >= 0; t--) {
            idx = (size_t)t * HWSZ;
            f = FT2[idx];
            C = f * C + (1.0f - f) * WX[idx];
            float r2 = RT2[idx];
            o[idx] = htl[t] + r2 * C + (1.0f - r2) * XX[idx];
        }
    }
}

extern "C" void kernel_launch(void* const* d_in, const int* in_sizes, int n_in,
                              void* d_out, int out_size)
{
    const float* x  = (const float*)d_in[0];   // [2,16,31,128,128]
    const float* cw = (const float*)d_in[1];   // [96,16,3,3,3]
    const float* cb = (const float*)d_in[2];   // [96]
    float* out = (float*)d_out;

    cudaFuncSetAttribute(conv_wino, cudaFuncAttributeMaxDynamicSharedMemorySize,
                         SMEM_DYN);

    prep_w<<<(16 * NOC * 48 + 255) / 256, 256>>>(cw);

    dim3 grd(WW / 16, HH / 8, BB * TT);        // (8, 16, 62) = 7936 CTAs
    conv_wino<<<grd, NTHR, SMEM_DYN>>>(x, cb);

    int n = BB * CG * HWSZ;
    sru_scan_kernel<<<n / 256, 256>>>(out);
}